// round 7
// baseline (speedup 1.0000x reference)
#include <cuda_runtime.h>

#define BB 64
#define NN 576
#define DD 768
#define KK 1024
#define NT 2
#define ROWS (BB * NN)          // 36864
#define NPAIR (BB * KK)         // 65536
#define OUT_MAIN (NPAIR * NT)   // 131072
#define NV4 (DD / 4)            // 192 float4 per row

// Per-row projections P[b*N+n] = {z.W0[:,0], z.W0[:,1], z.W1[:,0], z.W1[:,1]}
// where W0 = W[0:D,:], W1 = W[D:2D,:]. 576 KB static scratch (guard-safe).
__device__ float4 g_P[ROWS];

// Kernel 1: skinny projection GEMM [36864x768]x[768x4].
// Warp = 4 consecutive rows per iter; conflict-free component-major smem weights.
// Grid = 444 = 3 blocks/SM x 148 SMs: one full wave, fine-grained grid-stride
// so per-SM work is balanced (R6's 384-block grid gave 3-vs-2 blocks/SM -> +40%).
__global__ __launch_bounds__(256, 3) void partvit_project_kernel(
    const float* __restrict__ z, const float* __restrict__ W) {
    // Wc[c][i4] = {W[d][0], W[d][1], W[d+D][0], W[d+D][1]}, d = 4*i4 + c. 12 KB.
    __shared__ float4 Wc[4][NV4];
    for (int f = threadIdx.x; f < DD; f += 256) {
        int c = f / NV4, i4 = f - c * NV4;
        int d = 4 * i4 + c;
        Wc[c][i4] = make_float4(W[2 * d], W[2 * d + 1],
                                W[2 * (d + DD)], W[2 * (d + DD) + 1]);
    }
    __syncthreads();

    int lane = threadIdx.x & 31;
    int gw   = (blockIdx.x * blockDim.x + threadIdx.x) >> 5;
    int nw   = (gridDim.x * blockDim.x) >> 5;

    for (int it = gw; it < ROWS / 4; it += nw) {
        int row = it * 4;
        const float4* z4 = reinterpret_cast<const float4*>(z + (size_t)row * DD);

        float4 a0 = {0,0,0,0}, a1 = {0,0,0,0}, a2 = {0,0,0,0}, a3 = {0,0,0,0};
        #pragma unroll 1
        for (int j = 0; j < 6; j++) {
            int i4 = lane + 32 * j;
            float4 z0 = z4[0 * NV4 + i4];
            float4 z1 = z4[1 * NV4 + i4];
            float4 z2 = z4[2 * NV4 + i4];
            float4 z3 = z4[3 * NV4 + i4];
            float4 w0 = Wc[0][i4];
            float4 w1 = Wc[1][i4];
            float4 w2 = Wc[2][i4];
            float4 w3 = Wc[3][i4];
            a0.x += z0.x*w0.x + z0.y*w1.x + z0.z*w2.x + z0.w*w3.x;
            a0.y += z0.x*w0.y + z0.y*w1.y + z0.z*w2.y + z0.w*w3.y;
            a0.z += z0.x*w0.z + z0.y*w1.z + z0.z*w2.z + z0.w*w3.z;
            a0.w += z0.x*w0.w + z0.y*w1.w + z0.z*w2.w + z0.w*w3.w;
            a1.x += z1.x*w0.x + z1.y*w1.x + z1.z*w2.x + z1.w*w3.x;
            a1.y += z1.x*w0.y + z1.y*w1.y + z1.z*w2.y + z1.w*w3.y;
            a1.z += z1.x*w0.z + z1.y*w1.z + z1.z*w2.z + z1.w*w3.z;
            a1.w += z1.x*w0.w + z1.y*w1.w + z1.z*w2.w + z1.w*w3.w;
            a2.x += z2.x*w0.x + z2.y*w1.x + z2.z*w2.x + z2.w*w3.x;
            a2.y += z2.x*w0.y + z2.y*w1.y + z2.z*w2.y + z2.w*w3.y;
            a2.z += z2.x*w0.z + z2.y*w1.z + z2.z*w2.z + z2.w*w3.z;
            a2.w += z2.x*w0.w + z2.y*w1.w + z2.z*w2.w + z2.w*w3.w;
            a3.x += z3.x*w0.x + z3.y*w1.x + z3.z*w2.x + z3.w*w3.x;
            a3.y += z3.x*w0.y + z3.y*w1.y + z3.z*w2.y + z3.w*w3.y;
            a3.z += z3.x*w0.z + z3.y*w1.z + z3.z*w2.z + z3.w*w3.z;
            a3.w += z3.x*w0.w + z3.y*w1.w + z3.z*w2.w + z3.w*w3.w;
        }

        #pragma unroll
        for (int off = 16; off; off >>= 1) {
            a0.x += __shfl_xor_sync(0xffffffffu, a0.x, off);
            a0.y += __shfl_xor_sync(0xffffffffu, a0.y, off);
            a0.z += __shfl_xor_sync(0xffffffffu, a0.z, off);
            a0.w += __shfl_xor_sync(0xffffffffu, a0.w, off);
            a1.x += __shfl_xor_sync(0xffffffffu, a1.x, off);
            a1.y += __shfl_xor_sync(0xffffffffu, a1.y, off);
            a1.z += __shfl_xor_sync(0xffffffffu, a1.z, off);
            a1.w += __shfl_xor_sync(0xffffffffu, a1.w, off);
            a2.x += __shfl_xor_sync(0xffffffffu, a2.x, off);
            a2.y += __shfl_xor_sync(0xffffffffu, a2.y, off);
            a2.z += __shfl_xor_sync(0xffffffffu, a2.z, off);
            a2.w += __shfl_xor_sync(0xffffffffu, a2.w, off);
            a3.x += __shfl_xor_sync(0xffffffffu, a3.x, off);
            a3.y += __shfl_xor_sync(0xffffffffu, a3.y, off);
            a3.z += __shfl_xor_sync(0xffffffffu, a3.z, off);
            a3.w += __shfl_xor_sync(0xffffffffu, a3.w, off);
        }
        if (lane == 0) {
            g_P[row + 0] = a0;
            g_P[row + 1] = a1;
            g_P[row + 2] = a2;
            g_P[row + 3] = a3;
        }
    }
}

// Kernel 2: gather pairs of projections + bias. Launched with PDL: starts while
// kernel 1 drains, loads idx/bias early (independent of g_P), then grid-syncs
// before reading g_P. Indices are int32.
__global__ __launch_bounds__(256) void partvit_gather_kernel(
    const int* __restrict__ idx, const float* __restrict__ bh,
    float* __restrict__ out, int out_size) {
    int i = blockIdx.x * 256 + threadIdx.x;    // pair id in [0, B*K)

    int2 p = make_int2(0, 0);
    if (i < NPAIR) p = reinterpret_cast<const int2*>(idx)[i];
    float bh0 = bh[0], bh1 = bh[1];

    cudaGridDependencySynchronize();           // wait for kernel 1's g_P writes

    if (i >= NPAIR) return;
    int b = i >> 10;                            // i / KK
    int i0 = min(max(p.x, 0), NN - 1);
    int i1 = min(max(p.y, 0), NN - 1);

    float4 p0 = g_P[b * NN + i0];   // pair elem 0 -> W[0:D] halves (.x,.y)
    float4 p1 = g_P[b * NN + i1];   // pair elem 1 -> W[D:2D] halves (.z,.w)

    float2 o;
    o.x = p0.x + p1.z + bh0;
    o.y = p0.y + p1.w + bh1;
    reinterpret_cast<float2*>(out)[i] = o;

    // If the harness flattens the (out, indices) tuple, echo indices as f32.
    if (out_size >= OUT_MAIN + 2 * NPAIR) {
        out[OUT_MAIN + 2 * i + 0] = (float)p.x;
        out[OUT_MAIN + 2 * i + 1] = (float)p.y;
    }
}

extern "C" void kernel_launch(void* const* d_in, const int* in_sizes, int n_in,
                              void* d_out, int out_size) {
    const float* z   = (const float*)d_in[0];      // [B, N, D] f32
    const int*   idx = (const int*)d_in[1];        // [B, K, 2] i32
    const float* W   = (const float*)d_in[2];      // [2D, NT] f32
    const float* bh  = (const float*)d_in[3];      // [NT] f32
    float* out = (float*)d_out;

    partvit_project_kernel<<<444, 256>>>(z, W);    // 3 blocks/SM x 148, one wave

    // PDL launch for the gather: overlap its prologue with kernel 1's tail.
    cudaLaunchConfig_t cfg = {};
    cfg.gridDim  = dim3(NPAIR / 256, 1, 1);
    cfg.blockDim = dim3(256, 1, 1);
    cudaLaunchAttribute attr[1];
    attr[0].id = cudaLaunchAttributeProgrammaticStreamSerialization;
    attr[0].val.programmaticStreamSerializationAllowed = 1;
    cfg.attrs = attr;
    cfg.numAttrs = 1;
    cudaLaunchKernelEx(&cfg, partvit_gather_kernel, idx, bh, out, out_size);
}

// round 8
// speedup vs baseline: 1.0142x; 1.0142x over previous
#include <cuda_runtime.h>

#define BB 64
#define NN 576
#define DD 768
#define KK 1024
#define NT 2
#define ROWS (BB * NN)          // 36864
#define NPAIR (BB * KK)         // 65536
#define OUT_MAIN (NPAIR * NT)   // 131072
#define NV4 (DD / 4)            // 192 float4 per row
#define GRID 444                // 3 blocks/SM x 148 SMs: exactly one co-resident wave

// Per-row projections P[b*N+n] = {z.W0[:,0], z.W0[:,1], z.W1[:,0], z.W1[:,1]}.
__device__ float4 g_P[ROWS];
// Grid barrier counter. Monotonic across graph replays (generation counting),
// never reset -> deterministic, graph-safe.
__device__ unsigned int g_bar;

// Fused kernel: phase 1 projects all rows (proven loop from R5), device-wide
// barrier (all GRID blocks are co-resident by construction), phase 2 gathers.
// idx/bias are prefetched into registers BEFORE phase 1 so their DRAM latency
// hides under the streaming phase.
__global__ __launch_bounds__(256, 3) void partvit_fused_kernel(
    const float* __restrict__ z, const int* __restrict__ idx,
    const float* __restrict__ W, const float* __restrict__ bh,
    float* __restrict__ out, int out_size) {
    int gtid = blockIdx.x * 256 + threadIdx.x;

    // ---- Prefetch gather inputs (consumed after the barrier) ----
    int2 pr = make_int2(0, 0);
    if (gtid < NPAIR) pr = reinterpret_cast<const int2*>(idx)[gtid];
    float bh0 = bh[0], bh1 = bh[1];

    // ---- Phase 1: projection ----
    // Wc[c][i4] = {W[d][0], W[d][1], W[d+D][0], W[d+D][1]}, d = 4*i4 + c. 12 KB.
    __shared__ float4 Wc[4][NV4];
    for (int f = threadIdx.x; f < DD; f += 256) {
        int c = f / NV4, i4 = f - c * NV4;
        int d = 4 * i4 + c;
        Wc[c][i4] = make_float4(W[2 * d], W[2 * d + 1],
                                W[2 * (d + DD)], W[2 * (d + DD) + 1]);
    }
    __syncthreads();

    int lane = threadIdx.x & 31;
    int gw   = gtid >> 5;
    int nw   = (GRID * 256) >> 5;

    for (int it = gw; it < ROWS / 4; it += nw) {
        int row = it * 4;
        const float4* z4 = reinterpret_cast<const float4*>(z + (size_t)row * DD);

        float4 a0 = {0,0,0,0}, a1 = {0,0,0,0}, a2 = {0,0,0,0}, a3 = {0,0,0,0};
        #pragma unroll 1
        for (int j = 0; j < 6; j++) {
            int i4 = lane + 32 * j;
            float4 z0 = z4[0 * NV4 + i4];
            float4 z1 = z4[1 * NV4 + i4];
            float4 z2 = z4[2 * NV4 + i4];
            float4 z3 = z4[3 * NV4 + i4];
            float4 w0 = Wc[0][i4];
            float4 w1 = Wc[1][i4];
            float4 w2 = Wc[2][i4];
            float4 w3 = Wc[3][i4];
            a0.x += z0.x*w0.x + z0.y*w1.x + z0.z*w2.x + z0.w*w3.x;
            a0.y += z0.x*w0.y + z0.y*w1.y + z0.z*w2.y + z0.w*w3.y;
            a0.z += z0.x*w0.z + z0.y*w1.z + z0.z*w2.z + z0.w*w3.z;
            a0.w += z0.x*w0.w + z0.y*w1.w + z0.z*w2.w + z0.w*w3.w;
            a1.x += z1.x*w0.x + z1.y*w1.x + z1.z*w2.x + z1.w*w3.x;
            a1.y += z1.x*w0.y + z1.y*w1.y + z1.z*w2.y + z1.w*w3.y;
            a1.z += z1.x*w0.z + z1.y*w1.z + z1.z*w2.z + z1.w*w3.z;
            a1.w += z1.x*w0.w + z1.y*w1.w + z1.z*w2.w + z1.w*w3.w;
            a2.x += z2.x*w0.x + z2.y*w1.x + z2.z*w2.x + z2.w*w3.x;
            a2.y += z2.x*w0.y + z2.y*w1.y + z2.z*w2.y + z2.w*w3.y;
            a2.z += z2.x*w0.z + z2.y*w1.z + z2.z*w2.z + z2.w*w3.z;
            a2.w += z2.x*w0.w + z2.y*w1.w + z2.z*w2.w + z2.w*w3.w;
            a3.x += z3.x*w0.x + z3.y*w1.x + z3.z*w2.x + z3.w*w3.x;
            a3.y += z3.x*w0.y + z3.y*w1.y + z3.z*w2.y + z3.w*w3.y;
            a3.z += z3.x*w0.z + z3.y*w1.z + z3.z*w2.z + z3.w*w3.z;
            a3.w += z3.x*w0.w + z3.y*w1.w + z3.z*w2.w + z3.w*w3.w;
        }

        #pragma unroll
        for (int off = 16; off; off >>= 1) {
            a0.x += __shfl_xor_sync(0xffffffffu, a0.x, off);
            a0.y += __shfl_xor_sync(0xffffffffu, a0.y, off);
            a0.z += __shfl_xor_sync(0xffffffffu, a0.z, off);
            a0.w += __shfl_xor_sync(0xffffffffu, a0.w, off);
            a1.x += __shfl_xor_sync(0xffffffffu, a1.x, off);
            a1.y += __shfl_xor_sync(0xffffffffu, a1.y, off);
            a1.z += __shfl_xor_sync(0xffffffffu, a1.z, off);
            a1.w += __shfl_xor_sync(0xffffffffu, a1.w, off);
            a2.x += __shfl_xor_sync(0xffffffffu, a2.x, off);
            a2.y += __shfl_xor_sync(0xffffffffu, a2.y, off);
            a2.z += __shfl_xor_sync(0xffffffffu, a2.z, off);
            a2.w += __shfl_xor_sync(0xffffffffu, a2.w, off);
            a3.x += __shfl_xor_sync(0xffffffffu, a3.x, off);
            a3.y += __shfl_xor_sync(0xffffffffu, a3.y, off);
            a3.z += __shfl_xor_sync(0xffffffffu, a3.z, off);
            a3.w += __shfl_xor_sync(0xffffffffu, a3.w, off);
        }
        if (lane == 0) {
            g_P[row + 0] = a0;
            g_P[row + 1] = a1;
            g_P[row + 2] = a2;
            g_P[row + 3] = a3;
        }
    }

    // ---- Device-wide barrier (generation-counted, replay-safe) ----
    __syncthreads();
    if (threadIdx.x == 0) {
        __threadfence();                              // release g_P writes
        unsigned old = atomicAdd(&g_bar, 1u);
        unsigned target = (old / GRID) * GRID + GRID; // this generation's goal
        unsigned v;
        do {
            asm volatile("ld.global.acquire.gpu.u32 %0, [%1];"
                         : "=r"(v) : "l"(&g_bar));
            if ((int)(v - target) >= 0) break;
            __nanosleep(64);
        } while (true);
    }
    __syncthreads();                                  // broadcast release to block

    // ---- Phase 2: gather (pair gtid) ----
    if (gtid >= NPAIR) return;
    int b  = gtid >> 10;                              // gtid / KK
    int i0 = min(max(pr.x, 0), NN - 1);
    int i1 = min(max(pr.y, 0), NN - 1);

    float4 p0 = g_P[b * NN + i0];   // pair elem 0 -> W[0:D] halves (.x,.y)
    float4 p1 = g_P[b * NN + i1];   // pair elem 1 -> W[D:2D] halves (.z,.w)

    float2 o;
    o.x = p0.x + p1.z + bh0;
    o.y = p0.y + p1.w + bh1;
    reinterpret_cast<float2*>(out)[gtid] = o;

    // If the harness flattens the (out, indices) tuple, echo indices as f32.
    if (out_size >= OUT_MAIN + 2 * NPAIR) {
        out[OUT_MAIN + 2 * gtid + 0] = (float)pr.x;
        out[OUT_MAIN + 2 * gtid + 1] = (float)pr.y;
    }
}

extern "C" void kernel_launch(void* const* d_in, const int* in_sizes, int n_in,
                              void* d_out, int out_size) {
    const float* z   = (const float*)d_in[0];      // [B, N, D] f32
    const int*   idx = (const int*)d_in[1];        // [B, K, 2] i32
    const float* W   = (const float*)d_in[2];      // [2D, NT] f32
    const float* bh  = (const float*)d_in[3];      // [NT] f32
    float* out = (float*)d_out;

    partvit_fused_kernel<<<GRID, 256>>>(z, idx, W, bh, out, out_size);
}